// round 5
// baseline (speedup 1.0000x reference)
#include <cuda_runtime.h>

// Shape fixed by setup_inputs: x [8, 8192, 512] fp32, weight [512] fp32.
#define BB 8
#define TT 8192
#define CC 512
#define EPSF 1e-5f

#define THREADS 1024             // 32 warps
#define FPB 64                   // frames per block (tile = 128 KB smem)
#define BPB (TT / FPB)           // 128 blocks per batch
#define GRID (BB * BPB)          // 1024 blocks
#define FPW 2                    // frames per warp
#define SMEM_X_BYTES (FPB * CC * 4)

// Double-buffered published aggregates: low 32b = value, high 32b = flag.
// Statics zero-init, so parity 0 starts clean.
__device__ unsigned long long g_pubS1[2][GRID];
__device__ unsigned long long g_pubD[2][GRID];
__device__ int g_parity;
__device__ unsigned int g_done;

__device__ __forceinline__ void publish(unsigned long long* slot, float v) {
    *(volatile unsigned long long*)slot =
        (1ull << 32) | (unsigned long long)__float_as_uint(v);
}

// Warp-collective (warp 0): sum predecessor aggregates [0, kb) of this batch.
__device__ __forceinline__ float lookback(unsigned long long* base, int kb, int lane) {
    float v = 0.f;
    for (int idx = lane; idx < kb; idx += 32) {
        unsigned long long u;
        do {
            u = *(volatile unsigned long long*)&base[idx];
        } while (!(u >> 32));
        v += __uint_as_float((unsigned)u);
    }
#pragma unroll
    for (int o = 16; o > 0; o >>= 1) v += __shfl_xor_sync(0xffffffffu, v, o);
    return v;
}

__global__ void __launch_bounds__(THREADS, 1)
fused(const float* __restrict__ x, const float* __restrict__ w,
      float* __restrict__ out) {
    extern __shared__ float sX[];      // [FPB][CC]
    __shared__ float sS1[FPB];
    __shared__ float sQ[FPB];
    __shared__ float sMean[FPB];
    __shared__ float sInv[FPB];
    __shared__ float sW[CC];

    const int p = *(volatile int*)&g_parity;
    const int b = blockIdx.x / BPB;
    const int kb = blockIdx.x % BPB;
    const int wid = threadIdx.x >> 5;
    const int lane = threadIdx.x & 31;
    const size_t frame0 = (size_t)b * TT + (size_t)kb * FPB;

    // Clear the other parity's slots for the NEXT launch.
    if (threadIdx.x == 0) {
        *(volatile unsigned long long*)&g_pubS1[1 - p][blockIdx.x] = 0ull;
        *(volatile unsigned long long*)&g_pubD[1 - p][blockIdx.x] = 0ull;
    }

    // Weight -> shared.
    if (threadIdx.x < CC) sW[threadIdx.x] = w[threadIdx.x];

    // ---------------- Phase 1: gmem -> smem copy + per-frame reduce --------
    // Warp `wid` owns frames {2*wid, 2*wid+1}; lane handles 4 float4 each.
#pragma unroll
    for (int j = 0; j < FPW; j++) {
        const int f = wid * FPW + j;
        const float4* px = reinterpret_cast<const float4*>(x + (frame0 + f) * CC);
        float4* sx = reinterpret_cast<float4*>(sX + f * CC);
        float s = 0.f, q = 0.f;
#pragma unroll
        for (int k = 0; k < 4; k++) {
            float4 v = px[lane + k * 32];
            sx[lane + k * 32] = v;
            s += (v.x + v.y) + (v.z + v.w);
            q += v.x * v.x + v.y * v.y + v.z * v.z + v.w * v.w;
        }
#pragma unroll
        for (int o = 16; o > 0; o >>= 1) {
            s += __shfl_xor_sync(0xffffffffu, s, o);
            q += __shfl_xor_sync(0xffffffffu, q, o);
        }
        if (lane == 0) { sS1[f] = s; sQ[f] = q; }
    }
    __syncthreads();

    // ---------------- Warp 0: scans (2 frames/lane) + lookbacks ------------
    if (wid == 0) {
        const float a0 = sS1[2 * lane];
        const float a1 = sS1[2 * lane + 1];
        const float q0 = sQ[2 * lane];
        const float q1 = sQ[2 * lane + 1];

        // Inclusive scan of per-lane pair-sums.
        float pairsum = a0 + a1;
        float incl = pairsum;
#pragma unroll
        for (int o = 1; o < 32; o <<= 1) {
            float t = __shfl_up_sync(0xffffffffu, incl, o);
            if (lane >= o) incl += t;
        }
        if (lane == 31) publish(&g_pubS1[p][blockIdx.x], incl);
        const float exclB = lookback(&g_pubS1[p][b * BPB], kb, lane);
        const float exclL = incl - pairsum;  // lane-exclusive within block

        const int t0 = kb * FPB + 2 * lane;
        const float c0 = (float)(t0 + 1) * (float)CC;
        const float c1 = (float)(t0 + 2) * (float)CC;
        const float m0 = (exclB + exclL + a0) / c0;
        const float m1 = (exclB + exclL + a0 + a1) / c1;
        sMean[2 * lane] = m0;
        sMean[2 * lane + 1] = m1;

        // D = sum_c (x - m)^2 per frame; scan pairs.
        const float D0 = q0 - 2.f * m0 * a0 + (float)CC * m0 * m0;
        const float D1 = q1 - 2.f * m1 * a1 + (float)CC * m1 * m1;
        float dpair = D0 + D1;
        float dincl = dpair;
#pragma unroll
        for (int o = 1; o < 32; o <<= 1) {
            float t = __shfl_up_sync(0xffffffffu, dincl, o);
            if (lane >= o) dincl += t;
        }
        if (lane == 31) publish(&g_pubD[p][blockIdx.x], dincl);
        const float dExclB = lookback(&g_pubD[p][b * BPB], kb, lane);
        const float dExclL = dincl - dpair;

        const float v0 = (dExclB + dExclL + D0) / c0;
        const float v1 = (dExclB + dExclL + D0 + D1) / c1;
        sInv[2 * lane] = rsqrtf(v0 + EPSF);
        sInv[2 * lane + 1] = rsqrtf(v1 + EPSF);
    }
    __syncthreads();

    // ---------------- Phase 3: normalize from smem -------------------------
    const float4* w4 = reinterpret_cast<const float4*>(sW);
#pragma unroll
    for (int j = 0; j < FPW; j++) {
        const int f = wid * FPW + j;
        const float m = sMean[f];
        const float iv = sInv[f];
        const float4* sx = reinterpret_cast<const float4*>(sX + f * CC);
        float4* po = reinterpret_cast<float4*>(out + (frame0 + f) * CC);
#pragma unroll
        for (int k = 0; k < 4; k++) {
            float4 v = sx[lane + k * 32];
            float4 wv = w4[lane + k * 32];
            float4 r;
            r.x = (v.x - m) * iv * wv.x;
            r.y = (v.y - m) * iv * wv.y;
            r.z = (v.z - m) * iv * wv.z;
            r.w = (v.w - m) * iv * wv.w;
            __stcs(&po[lane + k * 32], r);
        }
    }

    // ---------------- Epilogue: last block flips parity --------------------
    __syncthreads();
    if (threadIdx.x == 0) {
        __threadfence();
        unsigned int n = atomicAdd(&g_done, 1u);
        if (n == GRID - 1) {
            g_done = 0;
            g_parity = p ^ 1;
        }
    }
}

extern "C" void kernel_launch(void* const* d_in, const int* in_sizes, int n_in,
                              void* d_out, int out_size) {
    const float* x = (const float*)d_in[0];
    const float* w = (const float*)d_in[1];
    float* out = (float*)d_out;

    cudaFuncSetAttribute(fused, cudaFuncAttributeMaxDynamicSharedMemorySize,
                         SMEM_X_BYTES);
    fused<<<GRID, THREADS, SMEM_X_BYTES>>>(x, w, out);
}